// round 4
// baseline (speedup 1.0000x reference)
#include <cuda_runtime.h>

// Problem constants
#define Bn   1024
#define Hn   256
#define Gn   768      // 3*H
#define On   512
#define Tn   60
#define Cc   15
#define TB   10       // samples per CTA tile
#define HP   12       // padded h row (48B, 16B-aligned)
#define K4   64       // Hn/4
#define MAXT 116      // sum_c ceil(n_c/TB) <= 115, padded

// Device scratch (allocation-free rule: static __device__ arrays)
// Packed k4-interleaved layouts: W_p[((c*K4 + k4)*COLS + g)*4 + j] = W[c][g][4*k4+j]
__device__ float g_Wi_p[Cc * K4 * Gn * 4];
__device__ float g_Wh_p[Cc * K4 * Gn * 4];
__device__ float g_Wc_p[Cc * K4 * On * 4];
__device__ int   g_perm[Bn];
__device__ int   g_tile_cam[MAXT];
__device__ int   g_tile_start[MAXT];
__device__ int   g_tile_cnt[MAXT];

typedef unsigned long long u64;

__device__ __forceinline__ u64 pack2(float a, float b) {
    u64 r;
    asm("mov.b64 %0, {%1, %2};" : "=l"(r)
        : "r"(__float_as_uint(a)), "r"(__float_as_uint(b)));
    return r;
}
__device__ __forceinline__ void fma2(u64 &d, u64 a, u64 b) {
    asm("fma.rn.f32x2 %0, %1, %2, %0;" : "+l"(d) : "l"(a), "l"(b));
}
__device__ __forceinline__ float2 unpack2(u64 v) {
    unsigned lo, hi;
    asm("mov.b64 {%0, %1}, %2;" : "=r"(lo), "=r"(hi) : "l"(v));
    return make_float2(__uint_as_float(lo), __uint_as_float(hi));
}
__device__ __forceinline__ float sigf(float v) {
    return 1.0f / (1.0f + __expf(-v));
}
__device__ __forceinline__ float tanh_f(float v) {
    return 2.0f * sigf(2.0f * v) - 1.0f;
}

// ---------------------------------------------------------------------------
// Kernel 0: counting-sort samples by camera, build tile table.
// ---------------------------------------------------------------------------
__global__ void bucket_kernel(const int* __restrict__ cam) {
    __shared__ int cnts[Cc], offs[Cc], curs[Cc];
    int tid = threadIdx.x;
    if (tid < Cc) cnts[tid] = 0;
    __syncthreads();
    for (int b = tid; b < Bn; b += blockDim.x)
        atomicAdd(&cnts[cam[b]], 1);
    __syncthreads();
    if (tid == 0) {
        int o = 0;
        for (int c = 0; c < Cc; c++) { offs[c] = o; curs[c] = o; o += cnts[c]; }
    }
    __syncthreads();
    for (int b = tid; b < Bn; b += blockDim.x) {
        int p = atomicAdd(&curs[cam[b]], 1);
        g_perm[p] = b;
    }
    __syncthreads();
    if (tid == 0) {
        int t = 0;
        for (int c = 0; c < Cc; c++) {
            for (int s = 0; s < cnts[c]; s += TB) {
                g_tile_cam[t]   = c;
                g_tile_start[t] = offs[c] + s;
                g_tile_cnt[t]   = min(TB, cnts[c] - s);
                t++;
            }
        }
        for (; t < MAXT; t++) g_tile_cnt[t] = 0;
    }
}

// ---------------------------------------------------------------------------
// Kernel 1: repack weights into k4-interleaved float4 layout.
// ---------------------------------------------------------------------------
__global__ void transpose_kernel(const float* __restrict__ Wi,
                                 const float* __restrict__ Wh,
                                 const float* __restrict__ Wc) {
    int idx    = blockIdx.x * blockDim.x + threadIdx.x;
    int stride = gridDim.x * blockDim.x;
    const int totA = Cc * K4 * Gn * 4;
    for (int i = idx; i < totA; i += stride) {
        int j  = i & 3;
        int g  = (i >> 2) % Gn;
        int k4 = ((i >> 2) / Gn) % K4;
        int c  = i / (4 * Gn * K4);
        int k  = 4 * k4 + j;
        g_Wi_p[i] = Wi[(c * Gn + g) * Hn + k];
        g_Wh_p[i] = Wh[(c * Gn + g) * Hn + k];
    }
    const int totC = Cc * K4 * On * 4;
    for (int i = idx; i < totC; i += stride) {
        int j  = i & 3;
        int o  = (i >> 2) % On;
        int k4 = ((i >> 2) / On) % K4;
        int c  = i / (4 * On * K4);
        int k  = 4 * k4 + j;
        g_Wc_p[i] = Wc[(c * On + o) * Hn + k];
    }
}

// ---------------------------------------------------------------------------
// Load 10 h values (one k-row, padded to HP=12) as 5 u64 sample-pairs:
// 2x LDS.128 (as ulonglong2) + 1x LDS.64. Zero repack instructions.
// ---------------------------------------------------------------------------
__device__ __forceinline__ void load_hrow(const float* row, u64 hv[5]) {
    ulonglong2 a = *reinterpret_cast<const ulonglong2*>(row);      // s0s1,s2s3
    ulonglong2 b = *reinterpret_cast<const ulonglong2*>(row + 4);  // s4s5,s6s7
    u64        c = *reinterpret_cast<const u64*>(row + 8);         // s8s9
    hv[0] = a.x; hv[1] = a.y; hv[2] = b.x; hv[3] = b.y; hv[4] = c;
}

// ---------------------------------------------------------------------------
// Main persistent kernel: one CTA per TB-sample same-camera tile.
// 512 threads, warp-specialized pipeline:
//   threads 0-255   (A): iter i computes h_{i+1} from h_i   (i < T)
//   threads 256-511 (B): iter i computes out_{i-1} from h_i (i > 0)
// One __syncthreads per iteration. Outputs staged in smem, flushed as
// STG.128 every 4 timesteps.
// ---------------------------------------------------------------------------
__global__ void __launch_bounds__(512, 1)
gru_main_kernel(const float* __restrict__ x,
                const float* __restrict__ b_ih,
                const float* __restrict__ b_hh,
                const float* __restrict__ bc,
                float* __restrict__ out) {
    extern __shared__ float sm[];
    float* sh_h  = sm;                         // [2][Hn][HP]  6144 floats
    float* sh_gi = sm + 2 * Hn * HP;           // [3][256][TB] 7680 floats
    float* sh_o  = sm + 2 * Hn * HP + 3 * 256 * TB;  // [256][2][TB][4] 20480 floats
    float* sh_x  = sh_o;                       // alias: setup-only lifetime [Hn][HP]
    int*   sh_samp = (int*)(sh_o + 256 * 2 * TB * 4);

    const int tile = blockIdx.x;
    const int cnt  = g_tile_cnt[tile];
    if (cnt == 0) return;
    const int cam   = g_tile_cam[tile];
    const int start = g_tile_start[tile];
    const int tid   = threadIdx.x;

    if (tid < TB) sh_samp[tid] = (tid < cnt) ? g_perm[start + tid] : 0;
    __syncthreads();

    // Init: x transposed into smem (zero-pad), both h buffers = 0.
    for (int i = tid; i < Hn * HP; i += 512) {
        int s = i % HP, k = i / HP;
        sh_x[i] = (s < cnt) ? x[sh_samp[s] * Hn + k] : 0.0f;  // pads s>=TB get garbage sample0? no: s<cnt only
        if (s >= cnt) sh_x[i] = 0.0f;
        sh_h[i] = 0.0f;
        sh_h[Hn * HP + i] = 0.0f;
    }
    __syncthreads();

    // ---- per-group setup --------------------------------------------------
    float bhn = 0.0f, bc0 = 0.0f, bc1 = 0.0f;
    int   ob[TB];

    if (tid < 256) {
        // A-group: gi = x @ Wi^T + b_ih (+ b_hh folded for r,z) -> smem.
        const int lt = tid;
        float aR[TB], aZ[TB], aN[TB];
#pragma unroll
        for (int s = 0; s < TB; s++) { aR[s] = 0.f; aZ[s] = 0.f; aN[s] = 0.f; }
        const float4* w = ((const float4*)g_Wi_p) + (size_t)cam * K4 * Gn;
        for (int k4 = 0; k4 < K4; k4++) {
            float4 w0 = w[lt], w1 = w[256 + lt], w2 = w[512 + lt];
            const float* f0 = (const float*)&w0;
            const float* f1 = (const float*)&w1;
            const float* f2 = (const float*)&w2;
#pragma unroll
            for (int j = 0; j < 4; j++) {
                const float* xk = &sh_x[(4 * k4 + j) * HP];
#pragma unroll
                for (int s = 0; s < TB; s++) {
                    float xv = xk[s];
                    aR[s] += f0[j] * xv;
                    aZ[s] += f1[j] * xv;
                    aN[s] += f2[j] * xv;
                }
            }
            w += Gn;
        }
        float br = b_ih[cam * Gn + lt]       + b_hh[cam * Gn + lt];
        float bz = b_ih[cam * Gn + 256 + lt] + b_hh[cam * Gn + 256 + lt];
        float bn = b_ih[cam * Gn + 512 + lt];
#pragma unroll
        for (int s = 0; s < TB; s++) {
            sh_gi[0 * 256 * TB + lt * TB + s] = aR[s] + br;
            sh_gi[1 * 256 * TB + lt * TB + s] = aZ[s] + bz;
            sh_gi[2 * 256 * TB + lt * TB + s] = aN[s] + bn;
        }
        bhn = b_hh[cam * Gn + 512 + lt];
    } else {
        const int lb = tid - 256;
        bc0 = bc[cam * On + lb];
        bc1 = bc[cam * On + 256 + lb];
#pragma unroll
        for (int s = 0; s < TB; s++) ob[s] = sh_samp[s] * (On * Tn);
    }

    const float4* whp = ((const float4*)g_Wh_p) + (size_t)cam * K4 * Gn;
    const float4* wcp = ((const float4*)g_Wc_p) + (size_t)cam * K4 * On;

    // ---- pipelined main loop: T+1 iterations ------------------------------
    for (int i = 0; i <= Tn; i++) {
        const int p = i & 1;
        const float* hb = sh_h + p * (Hn * HP);         // h_i (read-only)
        float*       hw = sh_h + (1 - p) * (Hn * HP);   // h_{i+1} (A writes)

        if (tid < 256) {
            if (i < Tn) {
                const int lt = tid;
                u64 aR[5], aZ[5], aN[5];
#pragma unroll
                for (int q = 0; q < 5; q++) { aR[q] = 0; aZ[q] = 0; aN[q] = 0; }
                const float4* w = whp;
#pragma unroll 2
                for (int k4 = 0; k4 < K4; k4++) {
                    float4 wr = w[lt], wz = w[256 + lt], wn = w[512 + lt];
                    w += Gn;
                    const float* fr = (const float*)&wr;
                    const float* fz = (const float*)&wz;
                    const float* fn = (const float*)&wn;
#pragma unroll
                    for (int j = 0; j < 4; j++) {
                        u64 hv[5];
                        load_hrow(hb + (4 * k4 + j) * HP, hv);
                        u64 r2 = pack2(fr[j], fr[j]);
                        u64 z2 = pack2(fz[j], fz[j]);
                        u64 n2 = pack2(fn[j], fn[j]);
#pragma unroll
                        for (int q = 0; q < 5; q++) {
                            fma2(aR[q], r2, hv[q]);
                            fma2(aZ[q], z2, hv[q]);
                            fma2(aN[q], n2, hv[q]);
                        }
                    }
                }
                // Gate epilogue -> h_{i+1}
                const float* hold = hb + lt * HP;
                float*       hnew = hw + lt * HP;
                const float* giR = &sh_gi[0 * 256 * TB + lt * TB];
                const float* giZ = &sh_gi[1 * 256 * TB + lt * TB];
                const float* giN = &sh_gi[2 * 256 * TB + lt * TB];
#pragma unroll
                for (int q = 0; q < 5; q++) {
                    float2 vR = unpack2(aR[q]);
                    float2 vZ = unpack2(aZ[q]);
                    float2 vN = unpack2(aN[q]);
                    int s0 = 2 * q, s1 = s0 + 1;
                    {
                        float r = sigf(giR[s0] + vR.x);
                        float z = sigf(giZ[s0] + vZ.x);
                        float n = tanh_f(giN[s0] + r * (vN.x + bhn));
                        hnew[s0] = (1.0f - z) * n + z * hold[s0];
                    }
                    {
                        float r = sigf(giR[s1] + vR.y);
                        float z = sigf(giZ[s1] + vZ.y);
                        float n = tanh_f(giN[s1] + r * (vN.y + bhn));
                        hnew[s1] = (1.0f - z) * n + z * hold[s1];
                    }
                }
            }
        } else {
            if (i > 0) {
                const int lb = tid - 256;
                const int t  = i - 1;
                u64 a0[5], a1[5];
#pragma unroll
                for (int q = 0; q < 5; q++) { a0[q] = 0; a1[q] = 0; }
                const float4* w = wcp;
#pragma unroll 2
                for (int k4 = 0; k4 < K4; k4++) {
                    float4 w0 = w[lb], w1 = w[256 + lb];
                    w += On;
                    const float* f0 = (const float*)&w0;
                    const float* f1 = (const float*)&w1;
#pragma unroll
                    for (int j = 0; j < 4; j++) {
                        u64 hv[5];
                        load_hrow(hb + (4 * k4 + j) * HP, hv);
                        u64 p0 = pack2(f0[j], f0[j]);
                        u64 p1 = pack2(f1[j], f1[j]);
#pragma unroll
                        for (int q = 0; q < 5; q++) {
                            fma2(a0[q], p0, hv[q]);
                            fma2(a1[q], p1, hv[q]);
                        }
                    }
                }
                // Stage sigmoid outputs into smem (thread-private slice).
                float* obuf = sh_o + lb * (2 * TB * 4);
                const int tq = t & 3;
#pragma unroll
                for (int q = 0; q < 5; q++) {
                    float2 v0 = unpack2(a0[q]);
                    float2 v1 = unpack2(a1[q]);
                    int s0 = 2 * q, s1 = s0 + 1;
                    obuf[(0 * TB + s0) * 4 + tq] = sigf(v0.x + bc0);
                    obuf[(1 * TB + s0) * 4 + tq] = sigf(v1.x + bc1);
                    obuf[(0 * TB + s1) * 4 + tq] = sigf(v0.y + bc0);
                    obuf[(1 * TB + s1) * 4 + tq] = sigf(v1.y + bc1);
                }
                // Flush every 4 timesteps with STG.128 (own slice, no barrier).
                if (tq == 3) {
                    const int t0 = t - 3;
#pragma unroll
                    for (int s = 0; s < TB; s++) {
                        if (s < cnt) {
                            float4 r0 = *reinterpret_cast<float4*>(&obuf[(0 * TB + s) * 4]);
                            float4 r1 = *reinterpret_cast<float4*>(&obuf[(1 * TB + s) * 4]);
                            *reinterpret_cast<float4*>(&out[ob[s] + lb * Tn + t0])         = r0;
                            *reinterpret_cast<float4*>(&out[ob[s] + (256 + lb) * Tn + t0]) = r1;
                        }
                    }
                }
            }
        }
        __syncthreads();   // publish h_{i+1}; retire reads of h_i
    }
}

// ---------------------------------------------------------------------------
extern "C" void kernel_launch(void* const* d_in, const int* in_sizes, int n_in,
                              void* d_out, int out_size) {
    const float* x    = (const float*)d_in[0];
    const int*   cam  = (const int*)  d_in[1];
    const float* W_ih = (const float*)d_in[2];
    const float* W_hh = (const float*)d_in[3];
    const float* b_ih = (const float*)d_in[4];
    const float* b_hh = (const float*)d_in[5];
    const float* Wc   = (const float*)d_in[6];
    const float* bc   = (const float*)d_in[7];
    float* out = (float*)d_out;

    const size_t smem = (size_t)(2 * Hn * HP + 3 * 256 * TB + 256 * 2 * TB * 4)
                        * sizeof(float) + 16 * sizeof(int);
    cudaFuncSetAttribute(gru_main_kernel,
                         cudaFuncAttributeMaxDynamicSharedMemorySize, (int)smem);

    bucket_kernel<<<1, 256>>>(cam);
    transpose_kernel<<<2048, 256>>>(W_ih, W_hh, Wc);
    gru_main_kernel<<<MAXT, 512, smem>>>(x, b_ih, b_hh, bc, out);
}

// round 5
// speedup vs baseline: 1.0346x; 1.0346x over previous
#include <cuda_runtime.h>

// Problem constants
#define Bn   1024
#define Hn   256
#define Gn   768      // 3*H
#define On   512
#define Tn   60
#define Cc   15
#define TB   10       // samples per CTA tile
#define HP   12       // padded h row (48B, 16B-aligned)
#define K4   64       // Hn/4
#define MAXT 116      // sum_c ceil(n_c/TB) <= 115, padded

// Device scratch (allocation-free rule: static __device__ arrays)
// Packed k4-interleaved layouts: W_p[((c*K4 + k4)*COLS + g)*4 + j] = W[c][g][4*k4+j]
// Padded by one k4 row so prefetch of k4+1 at k4=K4-1 stays in-bounds.
__device__ float g_Wi_p[Cc * K4 * Gn * 4 + Gn * 4];
__device__ float g_Wh_p[Cc * K4 * Gn * 4 + Gn * 4];
__device__ float g_Wc_p[Cc * K4 * On * 4 + On * 4];
__device__ int   g_perm[Bn];
__device__ int   g_tile_cam[MAXT];
__device__ int   g_tile_start[MAXT];
__device__ int   g_tile_cnt[MAXT];

typedef unsigned long long u64;

__device__ __forceinline__ u64 pack2(float a, float b) {
    u64 r;
    asm("mov.b64 %0, {%1, %2};" : "=l"(r)
        : "r"(__float_as_uint(a)), "r"(__float_as_uint(b)));
    return r;
}
__device__ __forceinline__ void fma2(u64 &d, u64 a, u64 b) {
    asm("fma.rn.f32x2 %0, %1, %2, %0;" : "+l"(d) : "l"(a), "l"(b));
}
__device__ __forceinline__ float2 unpack2(u64 v) {
    unsigned lo, hi;
    asm("mov.b64 {%0, %1}, %2;" : "=r"(lo), "=r"(hi) : "l"(v));
    return make_float2(__uint_as_float(lo), __uint_as_float(hi));
}
__device__ __forceinline__ float sigf(float v) {
    return 1.0f / (1.0f + __expf(-v));
}
__device__ __forceinline__ float tanh_f(float v) {
    return 2.0f * sigf(2.0f * v) - 1.0f;
}

// ---------------------------------------------------------------------------
// Kernel 0 (merged prep): all blocks repack weights (grid-stride); block 0
// additionally counting-sorts samples by camera and builds the tile table.
// Merging keeps launches/call at 2 so ncu's -s 5 lands on the main kernel.
// ---------------------------------------------------------------------------
__global__ void prep_kernel(const int* __restrict__ cam,
                            const float* __restrict__ Wi,
                            const float* __restrict__ Wh,
                            const float* __restrict__ Wc) {
    int idx    = blockIdx.x * blockDim.x + threadIdx.x;
    int stride = gridDim.x * blockDim.x;
    const int totA = Cc * K4 * Gn * 4;
    for (int i = idx; i < totA; i += stride) {
        int j  = i & 3;
        int g  = (i >> 2) % Gn;
        int k4 = ((i >> 2) / Gn) % K4;
        int c  = i / (4 * Gn * K4);
        int k  = 4 * k4 + j;
        g_Wi_p[i] = Wi[(c * Gn + g) * Hn + k];
        g_Wh_p[i] = Wh[(c * Gn + g) * Hn + k];
    }
    const int totC = Cc * K4 * On * 4;
    for (int i = idx; i < totC; i += stride) {
        int j  = i & 3;
        int o  = (i >> 2) % On;
        int k4 = ((i >> 2) / On) % K4;
        int c  = i / (4 * On * K4);
        int k  = 4 * k4 + j;
        g_Wc_p[i] = Wc[(c * On + o) * Hn + k];
    }

    if (blockIdx.x == 0) {
        __shared__ int cnts[Cc], offs[Cc], curs[Cc];
        int tid = threadIdx.x;
        if (tid < Cc) cnts[tid] = 0;
        __syncthreads();
        for (int b = tid; b < Bn; b += blockDim.x)
            atomicAdd(&cnts[cam[b]], 1);
        __syncthreads();
        if (tid == 0) {
            int o = 0;
            for (int c = 0; c < Cc; c++) { offs[c] = o; curs[c] = o; o += cnts[c]; }
        }
        __syncthreads();
        for (int b = tid; b < Bn; b += blockDim.x) {
            int p = atomicAdd(&curs[cam[b]], 1);
            g_perm[p] = b;
        }
        __syncthreads();
        if (tid == 0) {
            int t = 0;
            for (int c = 0; c < Cc; c++) {
                for (int s = 0; s < cnts[c]; s += TB) {
                    g_tile_cam[t]   = c;
                    g_tile_start[t] = offs[c] + s;
                    g_tile_cnt[t]   = min(TB, cnts[c] - s);
                    t++;
                }
            }
            for (; t < MAXT; t++) g_tile_cnt[t] = 0;
        }
    }
}

// ---------------------------------------------------------------------------
// Load 10 h values (one k-row, padded to HP=12) as 5 u64 sample-pairs.
// ---------------------------------------------------------------------------
__device__ __forceinline__ void load_hrow(const float* row, u64 hv[5]) {
    ulonglong2 a = *reinterpret_cast<const ulonglong2*>(row);      // s0s1,s2s3
    ulonglong2 b = *reinterpret_cast<const ulonglong2*>(row + 4);  // s4s5,s6s7
    u64        c = *reinterpret_cast<const u64*>(row + 8);         // s8s9
    hv[0] = a.x; hv[1] = a.y; hv[2] = b.x; hv[3] = b.y; hv[4] = c;
}

// ---------------------------------------------------------------------------
// Main persistent kernel: one CTA per TB-sample same-camera tile.
// 512 threads, warp-specialized pipeline:
//   threads 0-255   (A): iter i computes h_{i+1} from h_i   (i < T)
//   threads 256-511 (B): iter i computes out_{i-1} from h_i (i > 0)
// Weight loads are register-double-buffered (prefetch k4+1 while fma-ing k4)
// so L2 latency overlaps the fma2 pipe.
// ---------------------------------------------------------------------------
__global__ void __launch_bounds__(512, 1)
gru_main_kernel(const float* __restrict__ x,
                const float* __restrict__ b_ih,
                const float* __restrict__ b_hh,
                const float* __restrict__ bc,
                float* __restrict__ out) {
    extern __shared__ float sm[];
    float* sh_h  = sm;                         // [2][Hn][HP]  6144 floats
    float* sh_gi = sm + 2 * Hn * HP;           // [3][256][TB] 7680 floats
    float* sh_o  = sm + 2 * Hn * HP + 3 * 256 * TB;  // [256][2][TB][4] 20480 floats
    float* sh_x  = sh_o;                       // alias: setup-only lifetime [Hn][HP]
    int*   sh_samp = (int*)(sh_o + 256 * 2 * TB * 4);

    const int tile = blockIdx.x;
    const int cnt  = g_tile_cnt[tile];
    if (cnt == 0) return;
    const int cam   = g_tile_cam[tile];
    const int start = g_tile_start[tile];
    const int tid   = threadIdx.x;

    if (tid < TB) sh_samp[tid] = (tid < cnt) ? g_perm[start + tid] : 0;
    __syncthreads();

    // Init: x transposed into smem (zero-pad), both h buffers = 0.
    for (int i = tid; i < Hn * HP; i += 512) {
        int s = i % HP, k = i / HP;
        sh_x[i] = (s < cnt) ? x[sh_samp[s] * Hn + k] : 0.0f;
        sh_h[i] = 0.0f;
        sh_h[Hn * HP + i] = 0.0f;
    }
    __syncthreads();

    // ---- per-group setup --------------------------------------------------
    float bhn = 0.0f, bc0 = 0.0f, bc1 = 0.0f;
    int   ob[TB];

    if (tid < 256) {
        // A-group: gi = x @ Wi^T + b_ih (+ b_hh folded for r,z) -> smem.
        const int lt = tid;
        float aR[TB], aZ[TB], aN[TB];
#pragma unroll
        for (int s = 0; s < TB; s++) { aR[s] = 0.f; aZ[s] = 0.f; aN[s] = 0.f; }
        const float4* w = ((const float4*)g_Wi_p) + (size_t)cam * K4 * Gn;
        for (int k4 = 0; k4 < K4; k4++) {
            float4 w0 = w[lt], w1 = w[256 + lt], w2 = w[512 + lt];
            const float* f0 = (const float*)&w0;
            const float* f1 = (const float*)&w1;
            const float* f2 = (const float*)&w2;
#pragma unroll
            for (int j = 0; j < 4; j++) {
                const float* xk = &sh_x[(4 * k4 + j) * HP];
#pragma unroll
                for (int s = 0; s < TB; s++) {
                    float xv = xk[s];
                    aR[s] += f0[j] * xv;
                    aZ[s] += f1[j] * xv;
                    aN[s] += f2[j] * xv;
                }
            }
            w += Gn;
        }
        float br = b_ih[cam * Gn + lt]       + b_hh[cam * Gn + lt];
        float bz = b_ih[cam * Gn + 256 + lt] + b_hh[cam * Gn + 256 + lt];
        float bn = b_ih[cam * Gn + 512 + lt];
#pragma unroll
        for (int s = 0; s < TB; s++) {
            sh_gi[0 * 256 * TB + lt * TB + s] = aR[s] + br;
            sh_gi[1 * 256 * TB + lt * TB + s] = aZ[s] + bz;
            sh_gi[2 * 256 * TB + lt * TB + s] = aN[s] + bn;
        }
        bhn = b_hh[cam * Gn + 512 + lt];
    } else {
        const int lb = tid - 256;
        bc0 = bc[cam * On + lb];
        bc1 = bc[cam * On + 256 + lb];
#pragma unroll
        for (int s = 0; s < TB; s++) ob[s] = sh_samp[s] * (On * Tn);
    }

    const float4* whp = ((const float4*)g_Wh_p) + (size_t)cam * K4 * Gn;
    const float4* wcp = ((const float4*)g_Wc_p) + (size_t)cam * K4 * On;

    // ---- pipelined main loop: T+1 iterations ------------------------------
    for (int i = 0; i <= Tn; i++) {
        const int p = i & 1;
        const float* hb = sh_h + p * (Hn * HP);         // h_i (read-only)
        float*       hw = sh_h + (1 - p) * (Hn * HP);   // h_{i+1} (A writes)

        if (tid < 256) {
            if (i < Tn) {
                const int lt = tid;
                u64 aR[5], aZ[5], aN[5];
#pragma unroll
                for (int q = 0; q < 5; q++) { aR[q] = 0; aZ[q] = 0; aN[q] = 0; }
                const float4* w = whp;
                // prime the software pipeline
                float4 cR = w[lt], cZ = w[256 + lt], cN = w[512 + lt];
#pragma unroll 4
                for (int k4 = 0; k4 < K4; k4++) {
                    const float4* wn = w + Gn;
                    float4 nR = wn[lt], nZ = wn[256 + lt], nN = wn[512 + lt];
                    const float* fr = (const float*)&cR;
                    const float* fz = (const float*)&cZ;
                    const float* fn = (const float*)&cN;
#pragma unroll
                    for (int j = 0; j < 4; j++) {
                        u64 hv[5];
                        load_hrow(hb + (4 * k4 + j) * HP, hv);
                        u64 r2 = pack2(fr[j], fr[j]);
                        u64 z2 = pack2(fz[j], fz[j]);
                        u64 n2 = pack2(fn[j], fn[j]);
#pragma unroll
                        for (int q = 0; q < 5; q++) {
                            fma2(aR[q], r2, hv[q]);
                            fma2(aZ[q], z2, hv[q]);
                            fma2(aN[q], n2, hv[q]);
                        }
                    }
                    cR = nR; cZ = nZ; cN = nN;
                    w = wn;
                }
                // Gate epilogue -> h_{i+1}
                const float* hold = hb + lt * HP;
                float*       hnew = hw + lt * HP;
                const float* giR = &sh_gi[0 * 256 * TB + lt * TB];
                const float* giZ = &sh_gi[1 * 256 * TB + lt * TB];
                const float* giN = &sh_gi[2 * 256 * TB + lt * TB];
#pragma unroll
                for (int q = 0; q < 5; q++) {
                    float2 vR = unpack2(aR[q]);
                    float2 vZ = unpack2(aZ[q]);
                    float2 vN = unpack2(aN[q]);
                    int s0 = 2 * q, s1 = s0 + 1;
                    {
                        float r = sigf(giR[s0] + vR.x);
                        float z = sigf(giZ[s0] + vZ.x);
                        float n = tanh_f(giN[s0] + r * (vN.x + bhn));
                        hnew[s0] = (1.0f - z) * n + z * hold[s0];
                    }
                    {
                        float r = sigf(giR[s1] + vR.y);
                        float z = sigf(giZ[s1] + vZ.y);
                        float n = tanh_f(giN[s1] + r * (vN.y + bhn));
                        hnew[s1] = (1.0f - z) * n + z * hold[s1];
                    }
                }
            }
        } else {
            if (i > 0) {
                const int lb = tid - 256;
                const int t  = i - 1;
                u64 a0[5], a1[5];
#pragma unroll
                for (int q = 0; q < 5; q++) { a0[q] = 0; a1[q] = 0; }
                const float4* w = wcp;
                float4 c0 = w[lb], c1 = w[256 + lb];
#pragma unroll 4
                for (int k4 = 0; k4 < K4; k4++) {
                    const float4* wn = w + On;
                    float4 n0 = wn[lb], n1 = wn[256 + lb];
                    const float* f0 = (const float*)&c0;
                    const float* f1 = (const float*)&c1;
#pragma unroll
                    for (int j = 0; j < 4; j++) {
                        u64 hv[5];
                        load_hrow(hb + (4 * k4 + j) * HP, hv);
                        u64 p0 = pack2(f0[j], f0[j]);
                        u64 p1 = pack2(f1[j], f1[j]);
#pragma unroll
                        for (int q = 0; q < 5; q++) {
                            fma2(a0[q], p0, hv[q]);
                            fma2(a1[q], p1, hv[q]);
                        }
                    }
                    c0 = n0; c1 = n1;
                    w = wn;
                }
                // Stage sigmoid outputs into smem (thread-private slice).
                float* obuf = sh_o + lb * (2 * TB * 4);
                const int tq = t & 3;
#pragma unroll
                for (int q = 0; q < 5; q++) {
                    float2 v0 = unpack2(a0[q]);
                    float2 v1 = unpack2(a1[q]);
                    int s0 = 2 * q, s1 = s0 + 1;
                    obuf[(0 * TB + s0) * 4 + tq] = sigf(v0.x + bc0);
                    obuf[(1 * TB + s0) * 4 + tq] = sigf(v1.x + bc1);
                    obuf[(0 * TB + s1) * 4 + tq] = sigf(v0.y + bc0);
                    obuf[(1 * TB + s1) * 4 + tq] = sigf(v1.y + bc1);
                }
                // Flush every 4 timesteps with STG.128 (own slice, no barrier).
                if (tq == 3) {
                    const int t0 = t - 3;
#pragma unroll
                    for (int s = 0; s < TB; s++) {
                        if (s < cnt) {
                            float4 r0 = *reinterpret_cast<float4*>(&obuf[(0 * TB + s) * 4]);
                            float4 r1 = *reinterpret_cast<float4*>(&obuf[(1 * TB + s) * 4]);
                            *reinterpret_cast<float4*>(&out[ob[s] + lb * Tn + t0])         = r0;
                            *reinterpret_cast<float4*>(&out[ob[s] + (256 + lb) * Tn + t0]) = r1;
                        }
                    }
                }
            }
        }
        __syncthreads();   // publish h_{i+1}; retire reads of h_i
    }
}

// ---------------------------------------------------------------------------
extern "C" void kernel_launch(void* const* d_in, const int* in_sizes, int n_in,
                              void* d_out, int out_size) {
    const float* x    = (const float*)d_in[0];
    const int*   cam  = (const int*)  d_in[1];
    const float* W_ih = (const float*)d_in[2];
    const float* W_hh = (const float*)d_in[3];
    const float* b_ih = (const float*)d_in[4];
    const float* b_hh = (const float*)d_in[5];
    const float* Wc   = (const float*)d_in[6];
    const float* bc   = (const float*)d_in[7];
    float* out = (float*)d_out;

    const size_t smem = (size_t)(2 * Hn * HP + 3 * 256 * TB + 256 * 2 * TB * 4)
                        * sizeof(float) + 16 * sizeof(int);
    cudaFuncSetAttribute(gru_main_kernel,
                         cudaFuncAttributeMaxDynamicSharedMemorySize, (int)smem);

    prep_kernel<<<2048, 256>>>(cam, W_ih, W_hh, Wc);
    gru_main_kernel<<<MAXT, 512, smem>>>(x, b_ih, b_hh, bc, out);
}

// round 6
// speedup vs baseline: 1.0367x; 1.0020x over previous
#include <cuda_runtime.h>

// Problem constants
#define Bn   1024
#define Hn   256
#define Gn   768      // 3*H
#define On   512
#define Tn   60
#define Cc   15
#define TB   10       // samples per CTA tile
#define HP   12       // padded h row (48B, 16B-aligned)
#define K4   64       // Hn/4
#define MAXT 116      // sum_c ceil(n_c/TB) <= 115, padded

// Device scratch (allocation-free rule: static __device__ arrays)
// Packed k4-interleaved layouts: W_p[((c*K4 + k4)*COLS + g)*4 + j] = W[c][g][4*k4+j]
// Padded by one k4 row so prefetch of k4+1 at k4=K4-1 stays in-bounds.
__device__ float g_Wi_p[Cc * K4 * Gn * 4 + Gn * 4];
__device__ float g_Wh_p[Cc * K4 * Gn * 4 + Gn * 4];
__device__ float g_Wc_p[Cc * K4 * On * 4 + On * 4];
__device__ int   g_perm[Bn];
__device__ int   g_tile_cam[MAXT];
__device__ int   g_tile_start[MAXT];
__device__ int   g_tile_cnt[MAXT];

typedef unsigned long long u64;

__device__ __forceinline__ u64 pack2(float a, float b) {
    u64 r;
    asm("mov.b64 %0, {%1, %2};" : "=l"(r)
        : "r"(__float_as_uint(a)), "r"(__float_as_uint(b)));
    return r;
}
__device__ __forceinline__ void fma2(u64 &d, u64 a, u64 b) {
    asm("fma.rn.f32x2 %0, %1, %2, %0;" : "+l"(d) : "l"(a), "l"(b));
}
__device__ __forceinline__ float2 unpack2(u64 v) {
    unsigned lo, hi;
    asm("mov.b64 {%0, %1}, %2;" : "=r"(lo), "=r"(hi) : "l"(v));
    return make_float2(__uint_as_float(lo), __uint_as_float(hi));
}
__device__ __forceinline__ float sigf(float v) {
    return 1.0f / (1.0f + __expf(-v));
}
__device__ __forceinline__ float tanh_f(float v) {
    return 2.0f * sigf(2.0f * v) - 1.0f;
}

// ---------------------------------------------------------------------------
// Kernel 0 (merged prep): all blocks repack weights (grid-stride); block 0
// additionally counting-sorts samples by camera and builds the tile table.
// Merging keeps launches/call at 2 so ncu's -s 5 lands on the main kernel.
// ---------------------------------------------------------------------------
__global__ void prep_kernel(const int* __restrict__ cam,
                            const float* __restrict__ Wi,
                            const float* __restrict__ Wh,
                            const float* __restrict__ Wc) {
    int idx    = blockIdx.x * blockDim.x + threadIdx.x;
    int stride = gridDim.x * blockDim.x;
    const int totA = Cc * K4 * Gn * 4;
    for (int i = idx; i < totA; i += stride) {
        int j  = i & 3;
        int g  = (i >> 2) % Gn;
        int k4 = ((i >> 2) / Gn) % K4;
        int c  = i / (4 * Gn * K4);
        int k  = 4 * k4 + j;
        g_Wi_p[i] = Wi[(c * Gn + g) * Hn + k];
        g_Wh_p[i] = Wh[(c * Gn + g) * Hn + k];
    }
    const int totC = Cc * K4 * On * 4;
    for (int i = idx; i < totC; i += stride) {
        int j  = i & 3;
        int o  = (i >> 2) % On;
        int k4 = ((i >> 2) / On) % K4;
        int c  = i / (4 * On * K4);
        int k  = 4 * k4 + j;
        g_Wc_p[i] = Wc[(c * On + o) * Hn + k];
    }

    if (blockIdx.x == 0) {
        __shared__ int cnts[Cc], offs[Cc], curs[Cc];
        int tid = threadIdx.x;
        if (tid < Cc) cnts[tid] = 0;
        __syncthreads();
        for (int b = tid; b < Bn; b += blockDim.x)
            atomicAdd(&cnts[cam[b]], 1);
        __syncthreads();
        if (tid == 0) {
            int o = 0;
            for (int c = 0; c < Cc; c++) { offs[c] = o; curs[c] = o; o += cnts[c]; }
        }
        __syncthreads();
        for (int b = tid; b < Bn; b += blockDim.x) {
            int p = atomicAdd(&curs[cam[b]], 1);
            g_perm[p] = b;
        }
        __syncthreads();
        if (tid == 0) {
            int t = 0;
            for (int c = 0; c < Cc; c++) {
                for (int s = 0; s < cnts[c]; s += TB) {
                    g_tile_cam[t]   = c;
                    g_tile_start[t] = offs[c] + s;
                    g_tile_cnt[t]   = min(TB, cnts[c] - s);
                    t++;
                }
            }
            for (; t < MAXT; t++) g_tile_cnt[t] = 0;
        }
    }
}

// ---------------------------------------------------------------------------
// Load 10 h values (one k-row, padded to HP=12) as 5 u64 sample-pairs.
// ---------------------------------------------------------------------------
__device__ __forceinline__ void load_hrow(const float* row, u64 hv[5]) {
    ulonglong2 a = *reinterpret_cast<const ulonglong2*>(row);      // s0s1,s2s3
    ulonglong2 b = *reinterpret_cast<const ulonglong2*>(row + 4);  // s4s5,s6s7
    u64        c = *reinterpret_cast<const u64*>(row + 8);         // s8s9
    hv[0] = a.x; hv[1] = a.y; hv[2] = b.x; hv[3] = b.y; hv[4] = c;
}

// ---------------------------------------------------------------------------
// Main persistent kernel: one CTA per TB-sample same-camera tile.
// 512 threads, warp-specialized pipeline:
//   threads 0-255   (A): iter i computes h_{i+1} from h_i   (i < T)
//   threads 256-511 (B): iter i computes out_{i-1} from h_i (i > 0)
// Weight loads are register-double-buffered (prefetch k4+1 while fma-ing k4)
// so L2 latency overlaps the fma2 pipe.
// ---------------------------------------------------------------------------
__global__ void __launch_bounds__(512, 1)
gru_main_kernel(const float* __restrict__ x,
                const float* __restrict__ b_ih,
                const float* __restrict__ b_hh,
                const float* __restrict__ bc,
                float* __restrict__ out) {
    extern __shared__ float sm[];
    float* sh_h  = sm;                         // [2][Hn][HP]  6144 floats
    float* sh_gi = sm + 2 * Hn * HP;           // [3][256][TB] 7680 floats
    float* sh_o  = sm + 2 * Hn * HP + 3 * 256 * TB;  // [256][2][TB][4] 20480 floats
    float* sh_x  = sh_o;                       // alias: setup-only lifetime [Hn][HP]
    int*   sh_samp = (int*)(sh_o + 256 * 2 * TB * 4);

    const int tile = blockIdx.x;
    const int cnt  = g_tile_cnt[tile];
    if (cnt == 0) return;
    const int cam   = g_tile_cam[tile];
    const int start = g_tile_start[tile];
    const int tid   = threadIdx.x;

    if (tid < TB) sh_samp[tid] = (tid < cnt) ? g_perm[start + tid] : 0;
    __syncthreads();

    // Init: x transposed into smem (zero-pad), both h buffers = 0.
    for (int i = tid; i < Hn * HP; i += 512) {
        int s = i % HP, k = i / HP;
        sh_x[i] = (s < cnt) ? x[sh_samp[s] * Hn + k] : 0.0f;
        sh_h[i] = 0.0f;
        sh_h[Hn * HP + i] = 0.0f;
    }
    __syncthreads();

    // ---- per-group setup --------------------------------------------------
    float bhn = 0.0f, bc0 = 0.0f, bc1 = 0.0f;
    int   ob[TB];

    if (tid < 256) {
        // A-group: gi = x @ Wi^T + b_ih (+ b_hh folded for r,z) -> smem.
        const int lt = tid;
        float aR[TB], aZ[TB], aN[TB];
#pragma unroll
        for (int s = 0; s < TB; s++) { aR[s] = 0.f; aZ[s] = 0.f; aN[s] = 0.f; }
        const float4* w = ((const float4*)g_Wi_p) + (size_t)cam * K4 * Gn;
        for (int k4 = 0; k4 < K4; k4++) {
            float4 w0 = w[lt], w1 = w[256 + lt], w2 = w[512 + lt];
            const float* f0 = (const float*)&w0;
            const float* f1 = (const float*)&w1;
            const float* f2 = (const float*)&w2;
#pragma unroll
            for (int j = 0; j < 4; j++) {
                const float* xk = &sh_x[(4 * k4 + j) * HP];
#pragma unroll
                for (int s = 0; s < TB; s++) {
                    float xv = xk[s];
                    aR[s] += f0[j] * xv;
                    aZ[s] += f1[j] * xv;
                    aN[s] += f2[j] * xv;
                }
            }
            w += Gn;
        }
        float br = b_ih[cam * Gn + lt]       + b_hh[cam * Gn + lt];
        float bz = b_ih[cam * Gn + 256 + lt] + b_hh[cam * Gn + 256 + lt];
        float bn = b_ih[cam * Gn + 512 + lt];
#pragma unroll
        for (int s = 0; s < TB; s++) {
            sh_gi[0 * 256 * TB + lt * TB + s] = aR[s] + br;
            sh_gi[1 * 256 * TB + lt * TB + s] = aZ[s] + bz;
            sh_gi[2 * 256 * TB + lt * TB + s] = aN[s] + bn;
        }
        bhn = b_hh[cam * Gn + 512 + lt];
    } else {
        const int lb = tid - 256;
        bc0 = bc[cam * On + lb];
        bc1 = bc[cam * On + 256 + lb];
#pragma unroll
        for (int s = 0; s < TB; s++) ob[s] = sh_samp[s] * (On * Tn);
    }

    const float4* whp = ((const float4*)g_Wh_p) + (size_t)cam * K4 * Gn;
    const float4* wcp = ((const float4*)g_Wc_p) + (size_t)cam * K4 * On;

    // ---- pipelined main loop: T+1 iterations ------------------------------
    for (int i = 0; i <= Tn; i++) {
        const int p = i & 1;
        const float* hb = sh_h + p * (Hn * HP);         // h_i (read-only)
        float*       hw = sh_h + (1 - p) * (Hn * HP);   // h_{i+1} (A writes)

        if (tid < 256) {
            if (i < Tn) {
                const int lt = tid;
                u64 aR[5], aZ[5], aN[5];
#pragma unroll
                for (int q = 0; q < 5; q++) { aR[q] = 0; aZ[q] = 0; aN[q] = 0; }
                const float4* w = whp;
                // prime the software pipeline
                float4 cR = w[lt], cZ = w[256 + lt], cN = w[512 + lt];
#pragma unroll 4
                for (int k4 = 0; k4 < K4; k4++) {
                    const float4* wn = w + Gn;
                    float4 nR = wn[lt], nZ = wn[256 + lt], nN = wn[512 + lt];
                    const float* fr = (const float*)&cR;
                    const float* fz = (const float*)&cZ;
                    const float* fn = (const float*)&cN;
#pragma unroll
                    for (int j = 0; j < 4; j++) {
                        u64 hv[5];
                        load_hrow(hb + (4 * k4 + j) * HP, hv);
                        u64 r2 = pack2(fr[j], fr[j]);
                        u64 z2 = pack2(fz[j], fz[j]);
                        u64 n2 = pack2(fn[j], fn[j]);
#pragma unroll
                        for (int q = 0; q < 5; q++) {
                            fma2(aR[q], r2, hv[q]);
                            fma2(aZ[q], z2, hv[q]);
                            fma2(aN[q], n2, hv[q]);
                        }
                    }
                    cR = nR; cZ = nZ; cN = nN;
                    w = wn;
                }
                // Gate epilogue -> h_{i+1}
                const float* hold = hb + lt * HP;
                float*       hnew = hw + lt * HP;
                const float* giR = &sh_gi[0 * 256 * TB + lt * TB];
                const float* giZ = &sh_gi[1 * 256 * TB + lt * TB];
                const float* giN = &sh_gi[2 * 256 * TB + lt * TB];
#pragma unroll
                for (int q = 0; q < 5; q++) {
                    float2 vR = unpack2(aR[q]);
                    float2 vZ = unpack2(aZ[q]);
                    float2 vN = unpack2(aN[q]);
                    int s0 = 2 * q, s1 = s0 + 1;
                    {
                        float r = sigf(giR[s0] + vR.x);
                        float z = sigf(giZ[s0] + vZ.x);
                        float n = tanh_f(giN[s0] + r * (vN.x + bhn));
                        hnew[s0] = (1.0f - z) * n + z * hold[s0];
                    }
                    {
                        float r = sigf(giR[s1] + vR.y);
                        float z = sigf(giZ[s1] + vZ.y);
                        float n = tanh_f(giN[s1] + r * (vN.y + bhn));
                        hnew[s1] = (1.0f - z) * n + z * hold[s1];
                    }
                }
            }
        } else {
            if (i > 0) {
                const int lb = tid - 256;
                const int t  = i - 1;
                u64 a0[5], a1[5];
#pragma unroll
                for (int q = 0; q < 5; q++) { a0[q] = 0; a1[q] = 0; }
                const float4* w = wcp;
                float4 c0 = w[lb], c1 = w[256 + lb];
#pragma unroll 4
                for (int k4 = 0; k4 < K4; k4++) {
                    const float4* wn = w + On;
                    float4 n0 = wn[lb], n1 = wn[256 + lb];
                    const float* f0 = (const float*)&c0;
                    const float* f1 = (const float*)&c1;
#pragma unroll
                    for (int j = 0; j < 4; j++) {
                        u64 hv[5];
                        load_hrow(hb + (4 * k4 + j) * HP, hv);
                        u64 p0 = pack2(f0[j], f0[j]);
                        u64 p1 = pack2(f1[j], f1[j]);
#pragma unroll
                        for (int q = 0; q < 5; q++) {
                            fma2(a0[q], p0, hv[q]);
                            fma2(a1[q], p1, hv[q]);
                        }
                    }
                    c0 = n0; c1 = n1;
                    w = wn;
                }
                // Stage sigmoid outputs into smem (thread-private slice).
                float* obuf = sh_o + lb * (2 * TB * 4);
                const int tq = t & 3;
#pragma unroll
                for (int q = 0; q < 5; q++) {
                    float2 v0 = unpack2(a0[q]);
                    float2 v1 = unpack2(a1[q]);
                    int s0 = 2 * q, s1 = s0 + 1;
                    obuf[(0 * TB + s0) * 4 + tq] = sigf(v0.x + bc0);
                    obuf[(1 * TB + s0) * 4 + tq] = sigf(v1.x + bc1);
                    obuf[(0 * TB + s1) * 4 + tq] = sigf(v0.y + bc0);
                    obuf[(1 * TB + s1) * 4 + tq] = sigf(v1.y + bc1);
                }
                // Flush every 4 timesteps with STG.128 (own slice, no barrier).
                if (tq == 3) {
                    const int t0 = t - 3;
#pragma unroll
                    for (int s = 0; s < TB; s++) {
                        if (s < cnt) {
                            float4 r0 = *reinterpret_cast<float4*>(&obuf[(0 * TB + s) * 4]);
                            float4 r1 = *reinterpret_cast<float4*>(&obuf[(1 * TB + s) * 4]);
                            *reinterpret_cast<float4*>(&out[ob[s] + lb * Tn + t0])         = r0;
                            *reinterpret_cast<float4*>(&out[ob[s] + (256 + lb) * Tn + t0]) = r1;
                        }
                    }
                }
            }
        }
        __syncthreads();   // publish h_{i+1}; retire reads of h_i
    }
}

// ---------------------------------------------------------------------------
extern "C" void kernel_launch(void* const* d_in, const int* in_sizes, int n_in,
                              void* d_out, int out_size) {
    const float* x    = (const float*)d_in[0];
    const int*   cam  = (const int*)  d_in[1];
    const float* W_ih = (const float*)d_in[2];
    const float* W_hh = (const float*)d_in[3];
    const float* b_ih = (const float*)d_in[4];
    const float* b_hh = (const float*)d_in[5];
    const float* Wc   = (const float*)d_in[6];
    const float* bc   = (const float*)d_in[7];
    float* out = (float*)d_out;

    const size_t smem = (size_t)(2 * Hn * HP + 3 * 256 * TB + 256 * 2 * TB * 4)
                        * sizeof(float) + 16 * sizeof(int);
    cudaFuncSetAttribute(gru_main_kernel,
                         cudaFuncAttributeMaxDynamicSharedMemorySize, (int)smem);

    prep_kernel<<<2048, 256>>>(cam, W_ih, W_hh, Wc);
    gru_main_kernel<<<MAXT, 512, smem>>>(x, b_ih, b_hh, bc, out);
}